// round 1
// baseline (speedup 1.0000x reference)
#include <cuda_runtime.h>

// Problem constants (from reference)
#define N_TOKENS  65536
#define IN_DIM    2048
#define N_EXPERTS 64

// Tiling
#define BM 128   // tokens per CTA
#define BN 64    // experts per CTA (all of them)
#define BK 32    // K tile
#define TM 8     // tokens per thread
#define TN 4     // experts per thread
#define NTHREADS 256

#define LSTRIDE 65  // padded logits row stride (conflict-free epilogue reads)

__global__ __launch_bounds__(NTHREADS, 1)
void router_fused_kernel(const float* __restrict__ x,
                         const float* __restrict__ W,
                         float* __restrict__ out)
{
    // smem union: GEMM tiles (As 32*128 + Bs 32*64 = 6144 floats)
    //             vs epilogue logits Ls[128][65] = 8320 floats
    __shared__ float smem[BM * LSTRIDE];        // 8320 floats = 33,280 B
    __shared__ float rinv_sum[BM];              // 1/sum(exp) per token

    float* As = smem;               // [BK][BM], K-major-transposed
    float* Bs = smem + BK * BM;     // [BK][BN]

    const int tid = threadIdx.x;
    const int tx  = tid & 15;       // expert group  (0..15)
    const int ty  = tid >> 4;       // token group   (0..15)
    const int tokenBase = blockIdx.x * BM;

    float acc[TM][TN];
    #pragma unroll
    for (int i = 0; i < TM; i++)
        #pragma unroll
        for (int j = 0; j < TN; j++)
            acc[i][j] = 0.0f;

    const size_t xBase = (size_t)tokenBase * IN_DIM;

    for (int k0 = 0; k0 < IN_DIM; k0 += BK) {
        // ---- load x tile: 128 rows x 32 cols = 1024 float4, 4 per thread ----
        #pragma unroll
        for (int r = 0; r < 4; r++) {
            int idx = tid + NTHREADS * r;   // 0..1023
            int row = idx >> 3;             // 0..127
            int c4  = idx & 7;              // 0..7  (float4 column)
            float4 v = *(const float4*)(x + xBase + (size_t)row * IN_DIM + k0 + c4 * 4);
            int kk = c4 * 4;
            As[(kk + 0) * BM + row] = v.x;
            As[(kk + 1) * BM + row] = v.y;
            As[(kk + 2) * BM + row] = v.z;
            As[(kk + 3) * BM + row] = v.w;
        }
        // ---- load W tile: 64 rows x 32 cols = 512 float4, 2 per thread ----
        #pragma unroll
        for (int r = 0; r < 2; r++) {
            int idx = tid + NTHREADS * r;   // 0..511
            int row = idx >> 3;             // expert 0..63
            int c4  = idx & 7;
            float4 v = *(const float4*)(W + (size_t)row * IN_DIM + k0 + c4 * 4);
            int kk = c4 * 4;
            Bs[(kk + 0) * BN + row] = v.x;
            Bs[(kk + 1) * BN + row] = v.y;
            Bs[(kk + 2) * BN + row] = v.z;
            Bs[(kk + 3) * BN + row] = v.w;
        }
        __syncthreads();

        // ---- compute: 32 k-steps, 8x4 microtile ----
        #pragma unroll
        for (int k = 0; k < BK; k++) {
            float4 a0 = *(const float4*)(As + k * BM + ty * TM);
            float4 a1 = *(const float4*)(As + k * BM + ty * TM + 4);
            float4 bv = *(const float4*)(Bs + k * BN + tx * TN);
            float a[TM] = {a0.x, a0.y, a0.z, a0.w, a1.x, a1.y, a1.z, a1.w};
            float b[TN] = {bv.x, bv.y, bv.z, bv.w};
            #pragma unroll
            for (int i = 0; i < TM; i++)
                #pragma unroll
                for (int j = 0; j < TN; j++)
                    acc[i][j] = fmaf(a[i], b[j], acc[i][j]);
        }
        __syncthreads();
    }

    // ---- stash logits to padded smem ----
    float* Ls = smem;
    #pragma unroll
    for (int i = 0; i < TM; i++) {
        int t = ty * TM + i;
        #pragma unroll
        for (int j = 0; j < TN; j++)
            Ls[t * LSTRIDE + tx * TN + j] = acc[i][j];
    }
    __syncthreads();

    // ---- per-token softmax + top-2 (one thread per token) ----
    if (tid < BM) {
        float* row = Ls + tid * LSTRIDE;
        float mx = row[0];
        #pragma unroll
        for (int e = 1; e < N_EXPERTS; e++) mx = fmaxf(mx, row[e]);

        float sum = 0.0f;
        float v1 = -1.0f, v2 = -1.0f;   // exp values are in (0,1]
        int   i1 = 0,     i2 = 0;
        #pragma unroll
        for (int e = 0; e < N_EXPERTS; e++) {
            float p = __expf(row[e] - mx);
            row[e] = p;                  // store exp back for probs pass
            sum += p;
            if (p > v1)      { v2 = v1; i2 = i1; v1 = p; i1 = e; }
            else if (p > v2) { v2 = p;  i2 = e; }
        }
        rinv_sum[tid] = 1.0f / sum;

        const int token = tokenBase + tid;
        // layout: [0, 2N)   top_k_idx (as float)
        //         [2N, 4N)  top_k_weights (renormalized)
        //         [4N, 68N) router_probs
        float* outIdx = out;
        float* outW   = out + 2 * (size_t)N_TOKENS;
        outIdx[(size_t)token * 2 + 0] = (float)i1;
        outIdx[(size_t)token * 2 + 1] = (float)i2;
        float tw = 1.0f / (v1 + v2);    // softmax normalization cancels
        outW[(size_t)token * 2 + 0] = v1 * tw;
        outW[(size_t)token * 2 + 1] = v2 * tw;
    }
    __syncthreads();

    // ---- coalesced router_probs writes: 128 tokens x 64 experts ----
    float* probs = out + 4 * (size_t)N_TOKENS;
    const size_t pBase = (size_t)tokenBase * N_EXPERTS;
    #pragma unroll
    for (int r = 0; r < (BM * N_EXPERTS) / NTHREADS; r++) {   // 32 iters
        int idx = tid + NTHREADS * r;    // 0..8191
        int t = idx >> 6;                // token in tile
        int e = idx & 63;                // expert
        probs[pBase + idx] = Ls[t * LSTRIDE + e] * rinv_sum[t];
    }
}

extern "C" void kernel_launch(void* const* d_in, const int* in_sizes, int n_in,
                              void* d_out, int out_size)
{
    const float* x = (const float*)d_in[0];   // [65536, 2048] fp32
    const float* W = (const float*)d_in[1];   // [64, 2048]   fp32
    float* out = (float*)d_out;               // 68*N floats: idx | weights | probs

    dim3 grid(N_TOKENS / BM);   // 512
    dim3 block(NTHREADS);       // 256
    router_fused_kernel<<<grid, block>>>(x, W, out);
}

// round 3
// speedup vs baseline: 2.6096x; 2.6096x over previous
#include <cuda_runtime.h>
#include <cuda_fp16.h>
#include <cstdint>

// ---------------------------------------------------------------- constants
#define N_TOKENS  65536
#define IN_DIM    2048
#define N_EXPERTS 64
#define TILE_M    128
#define BK        32
#define NITER     (IN_DIM / BK)      // 64
#define NTHREADS  256
#define GRID_CTAS (N_TOKENS / TILE_M) // 512

// smem geometry (halves). Row stride 40 halves = 80 B: multiple of 16 B, and
// (20*r mod 32) distinct for r=0..7 -> conflict-free ldmatrix & STS.128.
#define ASTRIDE_H 40
#define A_TILE_B  (TILE_M * ASTRIDE_H * 2)      // 10240 B per split
#define B_TILE_B  (N_EXPERTS * ASTRIDE_H * 2)   // 5120 B per split
// stage layout (bytes): [A1 | A2 | B1 | B2]
#define OFF_A2    A_TILE_B                       // 10240
#define OFF_B1    (2 * A_TILE_B)                 // 20480
#define OFF_B2    (2 * A_TILE_B + B_TILE_B)      // 25600
#define STAGE_B   (2 * A_TILE_B + 2 * B_TILE_B)  // 30720
#define SMEM_BYTES (2 * STAGE_B)                 // 61440

#define SPLIT_SCALE 2048.0f
#define INV_SCALE   (1.0f / 2048.0f)

// W pack: [chunk j=0..63][split 0..1][n=0..63][k=0..31] fp16  (512 KB)
__device__ __align__(16) __half Wpack_g[NITER * 2 * N_EXPERTS * BK];

// ---------------------------------------------------------------- helpers
__device__ __forceinline__ uint32_t smem_u32(const void* p) {
    uint32_t a;
    asm("{ .reg .u64 t; cvta.to.shared.u64 t, %1; cvt.u32.u64 %0, t; }" : "=r"(a) : "l"(p));
    return a;
}

__device__ __forceinline__ void ldsm4(uint32_t& r0, uint32_t& r1, uint32_t& r2,
                                      uint32_t& r3, uint32_t addr) {
    asm volatile("ldmatrix.sync.aligned.m8n8.x4.shared.b16 {%0,%1,%2,%3}, [%4];"
                 : "=r"(r0), "=r"(r1), "=r"(r2), "=r"(r3) : "r"(addr));
}

__device__ __forceinline__ void mma16816(float* c, const uint32_t* a,
                                         uint32_t b0, uint32_t b1) {
    asm volatile(
        "mma.sync.aligned.m16n8k16.row.col.f32.f16.f16.f32 "
        "{%0,%1,%2,%3}, {%4,%5,%6,%7}, {%8,%9}, {%0,%1,%2,%3};"
        : "+f"(c[0]), "+f"(c[1]), "+f"(c[2]), "+f"(c[3])
        : "r"(a[0]), "r"(a[1]), "r"(a[2]), "r"(a[3]), "r"(b0), "r"(b1));
}

__device__ __forceinline__ void cp_async16(uint32_t dst, const void* src) {
    asm volatile("cp.async.ca.shared.global [%0], [%1], 16;" :: "r"(dst), "l"(src));
}
#define CP_COMMIT() asm volatile("cp.async.commit_group;" ::: "memory")
#define CP_WAIT0()  asm volatile("cp.async.wait_group 0;" ::: "memory")

// ---------------------------------------------------------------- W split pre-kernel
__global__ void wsplit_kernel(const float* __restrict__ W) {
    int idx = blockIdx.x * 256 + threadIdx.x;   // e*2048 + k, 131072 total
    int e = idx >> 11;
    int k = idx & 2047;
    float w = W[idx];
    __half h1 = __float2half_rn(w);
    float  r  = (w - __half2float(h1)) * SPLIT_SCALE;
    __half h2 = __float2half_rn(r);
    int j = k >> 5, kk = k & 31;
    // [j][split][n][k]
    Wpack_g[(size_t)j * 4096 + 0 * 2048 + e * 32 + kk] = h1;
    Wpack_g[(size_t)j * 4096 + 1 * 2048 + e * 32 + kk] = h2;
}

// ---------------------------------------------------------------- main kernel
extern __shared__ __align__(16) char smch[];

__global__ void __launch_bounds__(NTHREADS, 2)
router_mma_kernel(const float* __restrict__ x, float* __restrict__ out) {
    const int tid  = threadIdx.x;
    const int w    = tid >> 5;
    const int lane = tid & 31;
    const int tokenBase = blockIdx.x * TILE_M;
    const uint32_t sb = smem_u32(smch);

    // ---- per-thread x streaming map: row = tid/2, k-half = tid&1 (16 floats)
    const int xrow = tid >> 1;
    const int xh   = tid & 1;
    const float* xp = x + (size_t)(tokenBase + xrow) * IN_DIM + xh * 16;
    const uint32_t a_st_off = (uint32_t)xrow * 80 + (uint32_t)xh * 32; // bytes

    // ---- W cp.async map: thread handles segs tid (split0) and tid+256 (split1)
    const int wn  = (tid >> 2) & 63;
    const int wsk = tid & 3;
    const uint32_t b_dst0 = OFF_B1 + (uint32_t)wn * 80 + (uint32_t)wsk * 16;
    const uint32_t b_dst1 = OFF_B2 + (uint32_t)wn * 80 + (uint32_t)wsk * 16;

    // ---- ldmatrix offsets (bytes, stage-relative)
    const uint32_t a_ld_base = (uint32_t)(16 * w + ((lane >> 3) & 1) * 8 + (lane & 7)) * 80
                             + (uint32_t)((lane >> 4) & 1) * 16;
    const uint32_t b_ld_base = (uint32_t)(((lane >> 4) & 1) * 8 + (lane & 7)) * 80
                             + (uint32_t)((lane >> 3) & 1) * 16;

    float accM[32], accC[32];
    #pragma unroll
    for (int i = 0; i < 32; i++) { accM[i] = 0.0f; accC[i] = 0.0f; }

    float4 xr[4];

    // ================= prologue: fill stage 0 =================
    {
        const char* wsrc = (const char*)Wpack_g;  // chunk 0
        cp_async16(sb + b_dst0, wsrc + (size_t)tid * 16);
        cp_async16(sb + b_dst1, wsrc + (size_t)(tid + 256) * 16);
        CP_COMMIT();
        #pragma unroll
        for (int i = 0; i < 4; i++) xr[i] = *(const float4*)(xp + i * 4);
        // convert + store into stage 0
        __half2 h1[8], h2[8];
        #pragma unroll
        for (int i = 0; i < 4; i++) {
            float4 v = xr[i];
            __half2 a = __floats2half2_rn(v.x, v.y);
            __half2 b = __floats2half2_rn(v.z, v.w);
            float2 af = __half22float2(a), bf = __half22float2(b);
            h1[2*i] = a; h1[2*i+1] = b;
            h2[2*i]   = __floats2half2_rn((v.x - af.x) * SPLIT_SCALE, (v.y - af.y) * SPLIT_SCALE);
            h2[2*i+1] = __floats2half2_rn((v.z - bf.x) * SPLIT_SCALE, (v.w - bf.y) * SPLIT_SCALE);
        }
        char* Ab = smch;
        *(uint4*)(Ab + a_st_off)              = *(uint4*)&h1[0];
        *(uint4*)(Ab + a_st_off + 16)         = *(uint4*)&h1[4];
        *(uint4*)(Ab + OFF_A2 + a_st_off)     = *(uint4*)&h2[0];
        *(uint4*)(Ab + OFF_A2 + a_st_off + 16)= *(uint4*)&h2[4];
        CP_WAIT0();
        __syncthreads();
    }

    // ================= main loop =================
    for (int j = 0; j < NITER; j++) {
        const int s  = j & 1;
        const int nx = s ^ 1;
        const uint32_t stage = (uint32_t)s * STAGE_B;

        if (j + 1 < NITER) {
            const char* wsrc = (const char*)Wpack_g + (size_t)(j + 1) * 8192;
            const uint32_t nstage = (uint32_t)nx * STAGE_B;
            cp_async16(sb + nstage + b_dst0, wsrc + (size_t)tid * 16);
            cp_async16(sb + nstage + b_dst1, wsrc + (size_t)(tid + 256) * 16);
            CP_COMMIT();
            const float* xpn = xp + (j + 1) * BK;
            #pragma unroll
            for (int i = 0; i < 4; i++) xr[i] = *(const float4*)(xpn + i * 4);
        }

        // ---- compute stage s: 2 k16 steps x (A1,A2 x B-groups) ----
        #pragma unroll
        for (int kk2 = 0; kk2 < 2; kk2++) {
            const uint32_t ko = (uint32_t)kk2 * 32;
            uint32_t a1[4], a2[4];
            ldsm4(a1[0], a1[1], a1[2], a1[3], sb + stage + a_ld_base + ko);
            ldsm4(a2[0], a2[1], a2[2], a2[3], sb + stage + OFF_A2 + a_ld_base + ko);
            #pragma unroll
            for (int g = 0; g < 4; g++) {
                const uint32_t bo = b_ld_base + (uint32_t)g * 1280 + ko;
                uint32_t b1r[4], b2r[4];
                ldsm4(b1r[0], b1r[1], b1r[2], b1r[3], sb + stage + OFF_B1 + bo);
                ldsm4(b2r[0], b2r[1], b2r[2], b2r[3], sb + stage + OFF_B2 + bo);
                mma16816(&accM[(2*g)   * 4], a1, b1r[0], b1r[1]);
                mma16816(&accM[(2*g+1) * 4], a1, b1r[2], b1r[3]);
                mma16816(&accC[(2*g)   * 4], a1, b2r[0], b2r[1]);
                mma16816(&accC[(2*g+1) * 4], a1, b2r[2], b2r[3]);
                mma16816(&accC[(2*g)   * 4], a2, b1r[0], b1r[1]);
                mma16816(&accC[(2*g+1) * 4], a2, b1r[2], b1r[3]);
            }
        }

        if (j + 1 < NITER) {
            // convert + store x(j+1) into stage nx
            __half2 h1[8], h2[8];
            #pragma unroll
            for (int i = 0; i < 4; i++) {
                float4 v = xr[i];
                __half2 a = __floats2half2_rn(v.x, v.y);
                __half2 b = __floats2half2_rn(v.z, v.w);
                float2 af = __half22float2(a), bf = __half22float2(b);
                h1[2*i] = a; h1[2*i+1] = b;
                h2[2*i]   = __floats2half2_rn((v.x - af.x) * SPLIT_SCALE, (v.y - af.y) * SPLIT_SCALE);
                h2[2*i+1] = __floats2half2_rn((v.z - bf.x) * SPLIT_SCALE, (v.w - bf.y) * SPLIT_SCALE);
            }
            char* Ab = smch + (size_t)nx * STAGE_B;
            *(uint4*)(Ab + a_st_off)               = *(uint4*)&h1[0];
            *(uint4*)(Ab + a_st_off + 16)          = *(uint4*)&h1[4];
            *(uint4*)(Ab + OFF_A2 + a_st_off)      = *(uint4*)&h2[0];
            *(uint4*)(Ab + OFF_A2 + a_st_off + 16) = *(uint4*)&h2[4];
            CP_WAIT0();
        }
        __syncthreads();
    }

    // ================= epilogue =================
    // logits = main + cross/2048
    #pragma unroll
    for (int i = 0; i < 32; i++) accM[i] = fmaf(accC[i], INV_SCALE, accM[i]);

    const int q  = lane >> 2;   // row-in-8
    const int qc = lane & 3;    // column quad slot
    float* outIdx = out;
    float* outW   = out + 2 * (size_t)N_TOKENS;
    float* probs  = out + 4 * (size_t)N_TOKENS;

    #pragma unroll
    for (int r = 0; r < 2; r++) {
        float v[16];
        #pragma unroll
        for (int f = 0; f < 8; f++) {
            v[2*f]   = accM[f*4 + 2*r];
            v[2*f+1] = accM[f*4 + 2*r + 1];
        }
        // quad max
        float m = v[0];
        #pragma unroll
        for (int i = 1; i < 16; i++) m = fmaxf(m, v[i]);
        m = fmaxf(m, __shfl_xor_sync(0xffffffffu, m, 1));
        m = fmaxf(m, __shfl_xor_sync(0xffffffffu, m, 2));

        // local top-2 on logits (e ascending within lane -> strict > keeps lowest idx)
        float v1 = -3.4e38f, v2 = -3.4e38f;
        int   i1 = 0, i2 = 0;
        #pragma unroll
        for (int f = 0; f < 8; f++) {
            #pragma unroll
            for (int c = 0; c < 2; c++) {
                float val = v[2*f + c];
                int   e   = f * 8 + qc * 2 + c;
                if (val > v1)      { v2 = v1; i2 = i1; v1 = val; i1 = e; }
                else if (val > v2) { v2 = val; i2 = e; }
            }
        }
        // quad merge (tie -> lower index, matching jax)
        #pragma unroll
        for (int d = 1; d <= 2; d <<= 1) {
            float ov1 = __shfl_xor_sync(0xffffffffu, v1, d);
            int   oi1 = __shfl_xor_sync(0xffffffffu, i1, d);
            float ov2 = __shfl_xor_sync(0xffffffffu, v2, d);
            int   oi2 = __shfl_xor_sync(0xffffffffu, i2, d);
            bool bet1 = (ov1 > v1) || (ov1 == v1 && oi1 < i1);
            if (bet1) {
                bool keepOld = (v1 > ov2) || (v1 == ov2 && i1 < oi2);
                if (keepOld) { v2 = v1; i2 = i1; } else { v2 = ov2; i2 = oi2; }
                v1 = ov1; i1 = oi1;
            } else {
                bool bet2 = (ov1 > v2) || (ov1 == v2 && oi1 < i2);
                if (bet2) { v2 = ov1; i2 = oi1; }
            }
        }

        // exp + quad sum
        float s = 0.0f;
        #pragma unroll
        for (int i = 0; i < 16; i++) { v[i] = __expf(v[i] - m); s += v[i]; }
        s += __shfl_xor_sync(0xffffffffu, s, 1);
        s += __shfl_xor_sync(0xffffffffu, s, 2);
        float rinv = 1.0f / s;

        const int row = tokenBase + 16 * w + q + r * 8;
        float* pr = probs + (size_t)row * N_EXPERTS + qc * 2;
        #pragma unroll
        for (int f = 0; f < 8; f++) {
            float2 pv = make_float2(v[2*f] * rinv, v[2*f+1] * rinv);
            *(float2*)(pr + f * 8) = pv;
        }
        if (qc == 0) {
            float p1 = __expf(v1 - m), p2 = __expf(v2 - m);
            outIdx[(size_t)row * 2 + 0] = (float)i1;
            outIdx[(size_t)row * 2 + 1] = (float)i2;
            float tw = 1.0f / (p1 + p2);
            outW[(size_t)row * 2 + 0] = p1 * tw;
            outW[(size_t)row * 2 + 1] = p2 * tw;
        }
    }
}

// ---------------------------------------------------------------- launcher
extern "C" void kernel_launch(void* const* d_in, const int* in_sizes, int n_in,
                              void* d_out, int out_size) {
    const float* x = (const float*)d_in[0];   // [65536, 2048] fp32
    const float* W = (const float*)d_in[1];   // [64, 2048]   fp32
    float* out = (float*)d_out;

    static int configured = 0;
    if (!configured) {
        cudaFuncSetAttribute(router_mma_kernel,
                             cudaFuncAttributeMaxDynamicSharedMemorySize, SMEM_BYTES);
        configured = 1;
    }

    wsplit_kernel<<<(N_EXPERTS * IN_DIM) / 256, 256>>>(W);
    router_mma_kernel<<<GRID_CTAS, NTHREADS, SMEM_BYTES>>>(x, out);
}

// round 5
// speedup vs baseline: 3.3287x; 1.2755x over previous
#include <cuda_runtime.h>
#include <cuda_fp16.h>
#include <cstdint>

// ---------------------------------------------------------------- constants
#define N_TOKENS  65536
#define IN_DIM    2048
#define N_EXPERTS 64
#define TILE_M    256
#define BK        32
#define NITER     (IN_DIM / BK)       // 64
#define NTHREADS  256
#define GRID_CTAS (N_TOKENS / TILE_M) // 256

// smem stage layout (bytes). Row stride 40 halves = 80 B (20 words):
// 20*r mod 32 distinct for r=0..7 -> conflict-free ldmatrix.
// [ A_h1 256x80 | A_h2 256x80 | B_w1 64x80 | B_w2 64x80 ]
#define OFF_AR    20480
#define OFF_B1    40960
#define OFF_B2    46080
#define STAGE_B   51200
#define SMEM_BYTES (2 * STAGE_B)      // 102400

#define SPLIT_SCALE 2048.0f
#define INV_SCALE   (1.0f / 2048.0f)

// W pack: [chunk j=0..63][split 0..1][n=0..63][k=0..31] fp16 (512 KB)
// split0 = fp16(w), split1 = fp16((w - fp16(w)) * 2048)   (scaled: no subnormals)
__device__ __align__(16) __half Wpack_g[NITER * 2 * N_EXPERTS * BK];

// ---------------------------------------------------------------- helpers
__device__ __forceinline__ uint32_t smem_u32(const void* p) {
    uint32_t a;
    asm("{ .reg .u64 t; cvta.to.shared.u64 t, %1; cvt.u32.u64 %0, t; }" : "=r"(a) : "l"(p));
    return a;
}

__device__ __forceinline__ void ldsm4(uint32_t* r, uint32_t addr) {
    asm volatile("ldmatrix.sync.aligned.m8n8.x4.shared.b16 {%0,%1,%2,%3}, [%4];"
                 : "=r"(r[0]), "=r"(r[1]), "=r"(r[2]), "=r"(r[3]) : "r"(addr));
}

// fp32-accumulated main-bank MMA
__device__ __forceinline__ void mma_f32(float* c, const uint32_t* a,
                                        uint32_t b0, uint32_t b1) {
    asm volatile(
        "mma.sync.aligned.m16n8k16.row.col.f32.f16.f16.f32 "
        "{%0,%1,%2,%3}, {%4,%5,%6,%7}, {%8,%9}, {%0,%1,%2,%3};"
        : "+f"(c[0]), "+f"(c[1]), "+f"(c[2]), "+f"(c[3])
        : "r"(a[0]), "r"(a[1]), "r"(a[2]), "r"(a[3]), "r"(b0), "r"(b1));
}

// fp16-accumulated cross-bank MMA (2 C regs = 4 halves)
__device__ __forceinline__ void mma_f16(uint32_t* c, const uint32_t* a,
                                        uint32_t b0, uint32_t b1) {
    asm volatile(
        "mma.sync.aligned.m16n8k16.row.col.f16.f16.f16.f16 "
        "{%0,%1}, {%2,%3,%4,%5}, {%6,%7}, {%0,%1};"
        : "+r"(c[0]), "+r"(c[1])
        : "r"(a[0]), "r"(a[1]), "r"(a[2]), "r"(a[3]), "r"(b0), "r"(b1));
}

__device__ __forceinline__ void cp_async16(uint32_t dst, const void* src) {
    asm volatile("cp.async.ca.shared.global [%0], [%1], 16;" :: "r"(dst), "l"(src));
}
#define CP_COMMIT() asm volatile("cp.async.commit_group;" ::: "memory")
#define CP_WAIT0()  asm volatile("cp.async.wait_group 0;" ::: "memory")

// ---------------------------------------------------------------- W split pre-kernel
__global__ void wsplit_kernel(const float* __restrict__ W) {
    int idx = blockIdx.x * 256 + threadIdx.x;   // e*2048 + k
    int e = idx >> 11;
    int k = idx & 2047;
    float w = W[idx];
    __half h1 = __float2half_rn(w);
    float  r  = (w - __half2float(h1)) * SPLIT_SCALE;
    __half h2 = __float2half_rn(r);
    int j = k >> 5, kk = k & 31;
    Wpack_g[(size_t)j * 4096 + 0 * 2048 + e * 32 + kk] = h1;
    Wpack_g[(size_t)j * 4096 + 1 * 2048 + e * 32 + kk] = h2;
}

// ---------------------------------------------------------------- x conversion
// h1 = fp16(x); h2 = fp16((x - h1) * 2048)  -- scaled, stays in normal range
__device__ __forceinline__ void cvt_store(char* Ab, uint32_t off, float4 v) {
    __half2 h1a = __floats2half2_rn(v.x, v.y);
    __half2 h1b = __floats2half2_rn(v.z, v.w);
    float2 fa = __half22float2(h1a);
    float2 fb = __half22float2(h1b);
    __half2 ra = __floats2half2_rn((v.x - fa.x) * SPLIT_SCALE, (v.y - fa.y) * SPLIT_SCALE);
    __half2 rb = __floats2half2_rn((v.z - fb.x) * SPLIT_SCALE, (v.w - fb.y) * SPLIT_SCALE);
    uint2 hh, rr;
    hh.x = *(uint32_t*)&h1a; hh.y = *(uint32_t*)&h1b;
    rr.x = *(uint32_t*)&ra;  rr.y = *(uint32_t*)&rb;
    *(uint2*)(Ab + off)          = hh;
    *(uint2*)(Ab + OFF_AR + off) = rr;
}

// ---------------------------------------------------------------- main kernel
extern __shared__ __align__(16) char smch[];

__global__ void __launch_bounds__(NTHREADS, 1)
router_mma_kernel(const float* __restrict__ x, float* __restrict__ out) {
    const int tid  = threadIdx.x;
    const int w    = tid >> 5;
    const int lane = tid & 31;
    const int tokenBase = blockIdx.x * TILE_M;
    const uint32_t sb = smem_u32(smch);

    // ---- x LDG map: instr i covers rows w*32+i*4+(l>>3), float4 (l&7)
    //      -> each warp-LDG.128 touches 4 contiguous 128B lines.
    const float* xbase = x + (size_t)(tokenBase + w * 32 + (lane >> 3)) * IN_DIM
                           + (lane & 7) * 4;
    const uint32_t st_base = (uint32_t)((w * 32 + (lane >> 3)) * 80 + (lane & 7) * 8);

    // ---- W cp.async map
    const int wn  = (tid >> 2) & 63;
    const int wsk = tid & 3;
    const uint32_t b_dst0 = OFF_B1 + (uint32_t)wn * 80 + (uint32_t)wsk * 16;
    const uint32_t b_dst1 = OFF_B2 + (uint32_t)wn * 80 + (uint32_t)wsk * 16;

    // ---- ldmatrix offsets (stage-relative); warp owns rows [w*32, w*32+32)
    const uint32_t a_ld = (uint32_t)((w * 32 + (lane & 15)) * 80 + ((lane >> 4) & 1) * 16);
    const uint32_t b_ld = (uint32_t)(((lane & 7) + ((lane >> 4) & 1) * 8) * 80
                                     + ((lane >> 3) & 1) * 16);

    float    accM[2][32];    // fp32 main bank: h1*w1
    uint32_t accC[2][16];    // fp16 cross bank: h1*w2 + h2*w1 (cross units = x2048)
    #pragma unroll
    for (int m = 0; m < 2; m++) {
        #pragma unroll
        for (int i = 0; i < 32; i++) accM[m][i] = 0.0f;
        #pragma unroll
        for (int i = 0; i < 16; i++) accC[m][i] = 0u;
    }

    float4 xr[8];

    // ================= prologue: fill stage 0 =================
    {
        const char* wsrc = (const char*)Wpack_g;
        cp_async16(sb + b_dst0, wsrc + (size_t)tid * 16);
        cp_async16(sb + b_dst1, wsrc + (size_t)(tid + 256) * 16);
        CP_COMMIT();
        #pragma unroll
        for (int i = 0; i < 8; i++)
            xr[i] = *(const float4*)(xbase + (size_t)i * 4 * IN_DIM);
        char* Ab = smch;
        #pragma unroll
        for (int i = 0; i < 8; i++)
            cvt_store(Ab, st_base + (uint32_t)i * 320, xr[i]);
        CP_WAIT0();
        __syncthreads();
    }

    // ================= main loop =================
    for (int j = 0; j < NITER; j++) {
        const int s  = j & 1;
        const int nx = s ^ 1;
        const uint32_t stage = (uint32_t)s * STAGE_B;

        if (j + 1 < NITER) {
            const char* wsrc = (const char*)Wpack_g + (size_t)(j + 1) * 8192;
            const uint32_t nst = (uint32_t)nx * STAGE_B;
            cp_async16(sb + nst + b_dst0, wsrc + (size_t)tid * 16);
            cp_async16(sb + nst + b_dst1, wsrc + (size_t)(tid + 256) * 16);
            CP_COMMIT();
            #pragma unroll
            for (int i = 0; i < 8; i++)
                xr[i] = *(const float4*)(xbase + (size_t)i * 4 * IN_DIM + (j + 1) * BK);
        }

        // ---- compute stage s ----
        #pragma unroll
        for (int kk = 0; kk < 2; kk++) {
            const uint32_t ko = (uint32_t)kk * 32;
            uint32_t aH[2][4], aG[2][4];
            ldsm4(aH[0], sb + stage + a_ld + ko);
            ldsm4(aH[1], sb + stage + a_ld + 1280 + ko);            // +16 rows
            ldsm4(aG[0], sb + stage + OFF_AR + a_ld + ko);
            ldsm4(aG[1], sb + stage + OFF_AR + a_ld + 1280 + ko);
            #pragma unroll
            for (int g = 0; g < 4; g++) {
                const uint32_t bo = b_ld + (uint32_t)g * 1280 + ko;
                uint32_t w1[4], w2[4];
                ldsm4(w1, sb + stage + OFF_B1 + bo);
                ldsm4(w2, sb + stage + OFF_B2 + bo);
                #pragma unroll
                for (int m = 0; m < 2; m++) {
                    mma_f32(&accM[m][(2 * g) * 4],     aH[m], w1[0], w1[1]); // h1*w1
                    mma_f32(&accM[m][(2 * g + 1) * 4], aH[m], w1[2], w1[3]);
                    mma_f16(&accC[m][(2 * g) * 2],     aH[m], w2[0], w2[1]); // h1*w2
                    mma_f16(&accC[m][(2 * g + 1) * 2], aH[m], w2[2], w2[3]);
                    mma_f16(&accC[m][(2 * g) * 2],     aG[m], w1[0], w1[1]); // h2*w1
                    mma_f16(&accC[m][(2 * g + 1) * 2], aG[m], w1[2], w1[3]);
                }
            }
        }

        if (j + 1 < NITER) {
            char* Ab = smch + (size_t)nx * STAGE_B;
            #pragma unroll
            for (int i = 0; i < 8; i++)
                cvt_store(Ab, st_base + (uint32_t)i * 320, xr[i]);
            CP_WAIT0();
        }
        __syncthreads();
    }

    // ================= epilogue =================
    const int q  = lane >> 2;   // row-in-8
    const int qc = lane & 3;    // column quad slot
    float* outIdx = out;
    float* outW   = out + 2 * (size_t)N_TOKENS;
    float* probs  = out + 4 * (size_t)N_TOKENS;

    #pragma unroll
    for (int m = 0; m < 2; m++) {
        #pragma unroll
        for (int r = 0; r < 2; r++) {
            // logits = main + cross/2048
            float v[16];
            #pragma unroll
            for (int f = 0; f < 8; f++) {
                uint32_t cr = accC[m][f * 2 + r];
                float2 cf = __half22float2(*(__half2*)&cr);
                v[2 * f]     = fmaf(cf.x, INV_SCALE, accM[m][f * 4 + 2 * r]);
                v[2 * f + 1] = fmaf(cf.y, INV_SCALE, accM[m][f * 4 + 2 * r + 1]);
            }
            // quad max
            float mx = v[0];
            #pragma unroll
            for (int i = 1; i < 16; i++) mx = fmaxf(mx, v[i]);
            mx = fmaxf(mx, __shfl_xor_sync(0xffffffffu, mx, 1));
            mx = fmaxf(mx, __shfl_xor_sync(0xffffffffu, mx, 2));

            // local top-2 on logits (e ascending within lane)
            float v1 = -3.4e38f, v2 = -3.4e38f;
            int   i1 = 0, i2 = 0;
            #pragma unroll
            for (int f = 0; f < 8; f++) {
                #pragma unroll
                for (int c = 0; c < 2; c++) {
                    float val = v[2 * f + c];
                    int   e   = f * 8 + qc * 2 + c;
                    if (val > v1)      { v2 = v1; i2 = i1; v1 = val; i1 = e; }
                    else if (val > v2) { v2 = val; i2 = e; }
                }
            }
            // quad merge (tie -> lower index, matching jax)
            #pragma unroll
            for (int d = 1; d <= 2; d <<= 1) {
                float ov1 = __shfl_xor_sync(0xffffffffu, v1, d);
                int   oi1 = __shfl_xor_sync(0xffffffffu, i1, d);
                float ov2 = __shfl_xor_sync(0xffffffffu, v2, d);
                int   oi2 = __shfl_xor_sync(0xffffffffu, i2, d);
                bool bet1 = (ov1 > v1) || (ov1 == v1 && oi1 < i1);
                if (bet1) {
                    bool keepOld = (v1 > ov2) || (v1 == ov2 && i1 < oi2);
                    if (keepOld) { v2 = v1; i2 = i1; } else { v2 = ov2; i2 = oi2; }
                    v1 = ov1; i1 = oi1;
                } else {
                    bool bet2 = (ov1 > v2) || (ov1 == v2 && oi1 < i2);
                    if (bet2) { v2 = ov1; i2 = oi1; }
                }
            }

            // exp + quad sum
            float ssum = 0.0f;
            #pragma unroll
            for (int i = 0; i < 16; i++) { v[i] = __expf(v[i] - mx); ssum += v[i]; }
            ssum += __shfl_xor_sync(0xffffffffu, ssum, 1);
            ssum += __shfl_xor_sync(0xffffffffu, ssum, 2);
            float rinv = 1.0f / ssum;

            const int row = tokenBase + w * 32 + m * 16 + q + r * 8;
            float* pr = probs + (size_t)row * N_EXPERTS + qc * 2;
            #pragma unroll
            for (int f = 0; f < 8; f++) {
                float2 pv = make_float2(v[2 * f] * rinv, v[2 * f + 1] * rinv);
                *(float2*)(pr + f * 8) = pv;
            }
            if (qc == 0) {
                float p1 = __expf(v1 - mx), p2 = __expf(v2 - mx);
                outIdx[(size_t)row * 2 + 0] = (float)i1;
                outIdx[(size_t)row * 2 + 1] = (float)i2;
                float tw = 1.0f / (p1 + p2);
                outW[(size_t)row * 2 + 0] = p1 * tw;
                outW[(size_t)row * 2 + 1] = p2 * tw;
            }
        }
    }
}

// ---------------------------------------------------------------- launcher
extern "C" void kernel_launch(void* const* d_in, const int* in_sizes, int n_in,
                              void* d_out, int out_size) {
    const float* x = (const float*)d_in[0];   // [65536, 2048] fp32
    const float* W = (const float*)d_in[1];   // [64, 2048]   fp32
    float* out = (float*)d_out;

    static int configured = 0;
    if (!configured) {
        cudaFuncSetAttribute(router_mma_kernel,
                             cudaFuncAttributeMaxDynamicSharedMemorySize, SMEM_BYTES);
        configured = 1;
    }

    wsplit_kernel<<<(N_EXPERTS * IN_DIM) / 256, 256>>>(W);
    router_mma_kernel<<<GRID_CTAS, NTHREADS, SMEM_BYTES>>>(x, out);
}